// round 3
// baseline (speedup 1.0000x reference)
#include <cuda_runtime.h>

// CubicShapeFunction: 500K points, 4^3 cubic B-spline stencil.
// Output layout (flat float32):
//   [0, N*64)             shapef [N,64]
//   [N*64, N*64+N*192)    grad   [N,64,3]
//
// One thread handles (point, i, j, k=0..3): writes 1 float4 shapef + 3 float4 grad
// directly to global (all 16B-aligned). Spline table built once per point in SMEM.

constexpr int   N_POINTS      = 500000;
constexpr float INV_CELL      = 20.0f;
constexpr int   PTS_PER_BLOCK = 16;     // 500000 % 16 == 0
constexpr int   THREADS       = 256;    // 16 threads per point

__global__ __launch_bounds__(THREADS)
void cubic_shape_kernel(const float* __restrict__ pos, float* __restrict__ out) {
    // [pt][axis][offset]; s_b[p][2] starts at byte p*48+32 -> 16B aligned for LDS.128
    __shared__ float s_b [PTS_PER_BLOCK][3][4];
    __shared__ float s_db[PTS_PER_BLOCK][3][4];

    const int tid = threadIdx.x;
    const int pt0 = blockIdx.x * PTS_PER_BLOCK;

    // ---- Phase 1: 192 threads build the spline table (12 entries per point) ----
    if (tid < PTS_PER_BLOCK * 12) {
        const int p    = tid / 12;
        const int r    = tid % 12;
        const int axis = r >> 2;
        const int o    = r & 3;

        const float pp   = pos[(pt0 + p) * 3 + axis];
        const float rel  = pp * INV_CELL;                 // ORIGIN = 0
        const float base = floorf(rel) - 1.0f;
        const float x    = rel - (base + (float)o);       // matches reference expr

        float bb, dd;
        if (o == 0) {            // x in [1,2): c4 branch
            bb = (((-1.0f/6.0f) * x + 1.0f) * x - 2.0f) * x + 4.0f/3.0f;
            dd = (-0.5f * x + 2.0f) * x - 2.0f;
        } else if (o == 1) {     // x in [0,1): c3 branch
            bb = (0.5f * x - 1.0f) * x * x + 2.0f/3.0f;
            dd = (1.5f * x - 2.0f) * x;
        } else if (o == 2) {     // x in [-1,0): c2 branch
            bb = (-0.5f * x - 1.0f) * x * x + 2.0f/3.0f;
            dd = (-1.5f * x - 2.0f) * x;
        } else {                 // x in [-2,-1): c1 branch
            bb = (((1.0f/6.0f) * x + 1.0f) * x + 2.0f) * x + 4.0f/3.0f;
            dd = (0.5f * x + 2.0f) * x + 2.0f;
        }
        s_b [p][axis][o] = bb;
        s_db[p][axis][o] = INV_CELL * dd;
    }
    __syncthreads();

    // ---- Phase 2: thread = (point p, i, j), k vectorized -> 4 direct STG.128 ----
    const int p  = tid >> 4;       // 0..15
    const int ij = tid & 15;
    const int i  = ij >> 2;
    const int j  = ij & 3;

    const float bx  = s_b [p][0][i];
    const float by  = s_b [p][1][j];
    const float dbx = s_db[p][0][i];
    const float dby = s_db[p][1][j];
    const float4 bz  = *(const float4*)s_b [p][2];   // broadcast within point group
    const float4 dbz = *(const float4*)s_db[p][2];

    const float bxy   = bx * by;
    const float dbx_y = dbx * by;
    const float dby_x = dby * bx;

    const float4 sf = make_float4(bxy * bz.x, bxy * bz.y, bxy * bz.z, bxy * bz.w);

    // grad entry k: ( dbx*by*bz[k], dby*bx*bz[k], dbz[k]*bx*by )
    float4 g0 = make_float4(dbx_y * bz.x, dby_x * bz.x, dbz.x * bxy,
                            dbx_y * bz.y);
    float4 g1 = make_float4(dby_x * bz.y, dbz.y * bxy,
                            dbx_y * bz.z, dby_x * bz.z);
    float4 g2 = make_float4(dbz.z * bxy,
                            dbx_y * bz.w, dby_x * bz.w, dbz.w * bxy);

    const size_t pt = (size_t)(pt0 + p);
    float4* osf = (float4*)out;                               // shapef, 16 float4 per pt
    float4* ogr = (float4*)(out + (size_t)N_POINTS * 64);     // grad,   48 float4 per pt

    __stcs(&osf[pt * 16 + ij], sf);
    float4* g = &ogr[pt * 48 + ij * 3];
    __stcs(&g[0], g0);
    __stcs(&g[1], g1);
    __stcs(&g[2], g2);
}

extern "C" void kernel_launch(void* const* d_in, const int* in_sizes, int n_in,
                              void* d_out, int out_size) {
    const float* pos = (const float*)d_in[0];
    float* out = (float*)d_out;
    cubic_shape_kernel<<<N_POINTS / PTS_PER_BLOCK, THREADS>>>(pos, out);
}

// round 4
// speedup vs baseline: 1.4911x; 1.4911x over previous
#include <cuda_runtime.h>

// CubicShapeFunction: 500K points, 4^3 cubic B-spline stencil.
// Output layout (flat float32):
//   [0, N*64)             shapef [N,64]
//   [N*64, N*64+N*192)    grad   [N,64,3]
//
// R3: register math per (point,i,j) thread as in R2, but grad float4s are
// transposed through SMEM so every STG.128 is warp-coalesced (4 lines/store).

constexpr int   N_POINTS      = 500000;
constexpr float INV_CELL      = 20.0f;
constexpr int   PTS_PER_BLOCK = 16;     // 500000 % 16 == 0
constexpr int   THREADS       = 256;    // 16 threads per point

__global__ __launch_bounds__(THREADS)
void cubic_shape_kernel(const float* __restrict__ pos, float* __restrict__ out) {
    __shared__ float  s_b [PTS_PER_BLOCK][3][4];   // basis
    __shared__ float  s_db[PTS_PER_BLOCK][3][4];   // d(basis)*INV_CELL
    __shared__ float4 s_gr[PTS_PER_BLOCK * 48];    // 768 float4 = 12 KB grad staging

    const int tid = threadIdx.x;
    const int pt0 = blockIdx.x * PTS_PER_BLOCK;

    // ---- Phase 1: 192 threads build the spline table (12 entries per point) ----
    if (tid < PTS_PER_BLOCK * 12) {
        const int p    = tid / 12;
        const int r    = tid % 12;
        const int axis = r >> 2;
        const int o    = r & 3;

        const float pp   = pos[(pt0 + p) * 3 + axis];
        const float rel  = pp * INV_CELL;                 // ORIGIN = 0
        const float base = floorf(rel) - 1.0f;
        const float x    = rel - (base + (float)o);       // matches reference expr

        float bb, dd;
        if (o == 0) {            // x in [1,2): c4 branch
            bb = (((-1.0f/6.0f) * x + 1.0f) * x - 2.0f) * x + 4.0f/3.0f;
            dd = (-0.5f * x + 2.0f) * x - 2.0f;
        } else if (o == 1) {     // x in [0,1): c3 branch
            bb = (0.5f * x - 1.0f) * x * x + 2.0f/3.0f;
            dd = (1.5f * x - 2.0f) * x;
        } else if (o == 2) {     // x in [-1,0): c2 branch
            bb = (-0.5f * x - 1.0f) * x * x + 2.0f/3.0f;
            dd = (-1.5f * x - 2.0f) * x;
        } else {                 // x in [-2,-1): c1 branch
            bb = (((1.0f/6.0f) * x + 1.0f) * x + 2.0f) * x + 4.0f/3.0f;
            dd = (0.5f * x + 2.0f) * x + 2.0f;
        }
        s_b [p][axis][o] = bb;
        s_db[p][axis][o] = INV_CELL * dd;
    }
    __syncthreads();

    // ---- Phase 2: thread = (point p, i, j); k vectorized ----
    {
        const int p  = tid >> 4;       // 0..15
        const int ij = tid & 15;
        const int i  = ij >> 2;
        const int j  = ij & 3;

        const float bx  = s_b [p][0][i];
        const float by  = s_b [p][1][j];
        const float dbx = s_db[p][0][i];
        const float dby = s_db[p][1][j];
        const float4 bz  = *(const float4*)s_b [p][2];
        const float4 dbz = *(const float4*)s_db[p][2];

        const float bxy   = bx * by;
        const float dbx_y = dbx * by;
        const float dby_x = dby * bx;

        // shapef: directly coalesced (consecutive tid -> consecutive float4)
        const float4 sf = make_float4(bxy * bz.x, bxy * bz.y, bxy * bz.z, bxy * bz.w);
        float4* osf = (float4*)out;
        __stcs(&osf[(size_t)(pt0) * 16 + tid], sf);

        // grad entry k: ( dbx*by*bz[k], dby*bx*bz[k], dbz[k]*bx*by )
        float4 g0 = make_float4(dbx_y * bz.x, dby_x * bz.x, dbz.x * bxy,
                                dbx_y * bz.y);
        float4 g1 = make_float4(dby_x * bz.y, dbz.y * bxy,
                                dbx_y * bz.z, dby_x * bz.z);
        float4 g2 = make_float4(dbz.z * bxy,
                                dbx_y * bz.w, dby_x * bz.w, dbz.w * bxy);

        // stage grad in SMEM (stride-3 float4 across lanes: bank-conflict-free)
        float4* g = &s_gr[tid * 3];
        g[0] = g0;
        g[1] = g1;
        g[2] = g2;
    }
    __syncthreads();

    // ---- Phase 3: coalesced grad drain (3 x STG.128 per thread) ----
    {
        float4* ogr = (float4*)(out + (size_t)N_POINTS * 64)
                    + (size_t)blockIdx.x * (PTS_PER_BLOCK * 48);
        #pragma unroll
        for (int r = 0; r < 3; r++) {
            const int idx = r * THREADS + tid;
            __stcs(&ogr[idx], s_gr[idx]);
        }
    }
}

extern "C" void kernel_launch(void* const* d_in, const int* in_sizes, int n_in,
                              void* d_out, int out_size) {
    const float* pos = (const float*)d_in[0];
    float* out = (float*)d_out;
    cubic_shape_kernel<<<N_POINTS / PTS_PER_BLOCK, THREADS>>>(pos, out);
}